// round 3
// baseline (speedup 1.0000x reference)
#include <cuda_runtime.h>
#include <math.h>

#define BATCH 16
#define NCLS 90
#define NANCH 9
#define KSEL 5000
#define NSLOT 5120
#define SORTN 8192
#define NDET 100
#define CAND_CAP 131072
#define STAGE_CAP 2048
#define S_TARGET 384

typedef unsigned long long u64;
typedef unsigned int u32;

// ---------------- device scratch (static, no runtime alloc) ----------------
__device__ u32   g_hist[BATCH][2048];
__device__ float g_thr[BATCH];
__device__ int   g_cand_cnt[BATCH];
__device__ float g_cand_val[BATCH][CAND_CAP];
__device__ int   g_cand_idx[BATCH][CAND_CAP];
__device__ int   g_sel_cnt[BATCH];
__device__ float g_sel_val[BATCH][KSEL];
__device__ int   g_sel_idx[BATCH][KSEL];
__device__ float4 g_nms_box[BATCH][NSLOT];
__device__ float  g_nms_score[BATCH][NSLOT];
__device__ int    g_nms_cls[BATCH][NSLOT];

__device__ __forceinline__ u32 fkey(float f) {
    u32 u = __float_as_uint(f);
    return u ^ ((u32)((int)u >> 31) | 0x80000000u);   // monotonic: f1<f2 <=> key1<key2
}
__device__ __forceinline__ float ikey(u32 k) {
    u32 u = (k & 0x80000000u) ? (k ^ 0x80000000u) : ~k;
    return __uint_as_float(u);
}

// ---------------- kernel 0: zero counters/hist ----------------
__global__ void k_zero() {
    int t = blockIdx.x * blockDim.x + threadIdx.x;
    if (t < BATCH * 2048) ((u32*)g_hist)[t] = 0;
    if (t < BATCH) { g_cand_cnt[t] = 0; g_sel_cnt[t] = 0; }
}

// ---------------- kernel 1: sampled histogram (1/64 of elements) ----------------
__global__ void k_sample(const float* __restrict__ cls, int chw, int ns) {
    int t = blockIdx.x * blockDim.x + threadIdx.x;
    if (t >= BATCH * ns) return;
    int b = t / ns;
    int i = t - b * ns;
    int off = i * 256;
    if (off + 4 > chw) return;
    float4 v = __ldg((const float4*)(cls + (long)b * chw + off));
    atomicAdd(&g_hist[b][fkey(v.x) >> 21], 1u);
    atomicAdd(&g_hist[b][fkey(v.y) >> 21], 1u);
    atomicAdd(&g_hist[b][fkey(v.z) >> 21], 1u);
    atomicAdd(&g_hist[b][fkey(v.w) >> 21], 1u);
}

// ---------------- kernel 2: per-image threshold from sample hist ----------------
__global__ void k_thresh() {
    int b = threadIdx.x;
    if (b >= BATCH) return;
    u32 cum = 0;
    int bin = 2047;
    for (; bin >= 0; --bin) {
        cum += g_hist[b][bin];
        if (cum >= S_TARGET) break;
    }
    if (bin < 0) bin = 0;
    u32 kthr = ((u32)bin) << 21;
    u32 u = (kthr & 0x80000000u) ? (kthr ^ 0x80000000u) : ~kthr;
    g_thr[b] = __uint_as_float(u);
}

// ---------------- kernel 3: full scan + compaction of candidates ----------------
__global__ void k_compact(const float* __restrict__ cls, int chw4,
                          int shHW, int aoff) {
    __shared__ float s_val[STAGE_CAP];
    __shared__ int   s_idx[STAGE_CAP];
    __shared__ int   s_cnt, s_base;
    int b = blockIdx.y;
    int tid = threadIdx.x;
    if (tid == 0) s_cnt = 0;
    __syncthreads();
    float thr = g_thr[b];
    const float4* base = (const float4*)cls + (long)b * chw4;
    int blk = blockIdx.x * 2048;
    #pragma unroll
    for (int g = 0; g < 8; g++) {
        int i4 = blk + g * 256 + tid;
        if (i4 < chw4) {
            float4 v = __ldg(base + i4);
            #pragma unroll
            for (int j = 0; j < 4; j++) {
                float f = (j == 0) ? v.x : (j == 1) ? v.y : (j == 2) ? v.z : v.w;
                if (f >= thr) {
                    int lin = i4 * 4 + j;
                    int ch = lin >> shHW;                 // 0..809 (= a*90 + c)
                    int pix = lin & ((1 << shHW) - 1);    // h*W + w
                    int a = ch / NCLS;
                    int c = ch - a * NCLS;
                    int flat = (aoff + pix * NANCH + a) * NCLS + c;
                    int p = atomicAdd(&s_cnt, 1);
                    if (p < STAGE_CAP) { s_val[p] = f; s_idx[p] = flat; }
                }
            }
        }
    }
    __syncthreads();
    if (tid == 0) {
        int n = min(s_cnt, STAGE_CAP);
        s_base = atomicAdd(&g_cand_cnt[b], n);
        s_cnt = n;
    }
    __syncthreads();
    for (int i = tid; i < s_cnt; i += 256) {
        int gi = s_base + i;
        if (gi < CAND_CAP) {
            g_cand_val[b][gi] = s_val[i];
            g_cand_idx[b][gi] = s_idx[i];
        }
    }
}

// ---------------- kernel 4: exact top-K select + bitonic sort ----------------
extern __shared__ unsigned char k_select_dyn[];
__global__ void __launch_bounds__(1024, 1) k_select() {
    u32* hist = (u32*)k_select_dyn;       // 4096 u32 during radix rounds
    u64* skey = (u64*)k_select_dyn;       // 8192 u64 during sort (aliased)
    __shared__ int sb_B1, sb_cntAbove, sb_need2;
    __shared__ u32 sb_P;
    __shared__ int s_tie_cnt, s_out_cnt;
    __shared__ u32 s_tie_key[1024];
    __shared__ int s_tie_idx[1024];
    __shared__ unsigned char s_tie_sel[1024];

    int b = blockIdx.x;
    int tid = threadIdx.x;
    int m = min(g_cand_cnt[b], CAND_CAP);

    // round 1: histogram of top 12 key bits
    for (int i = tid; i < 4096; i += 1024) hist[i] = 0;
    if (tid == 0) { s_tie_cnt = 0; s_out_cnt = 0; }
    __syncthreads();
    for (int i = tid; i < m; i += 1024)
        atomicAdd(&hist[fkey(g_cand_val[b][i]) >> 20], 1u);
    __syncthreads();
    if (tid == 0) {
        u32 cum = 0; int bin = 4095;
        for (; bin >= 0; --bin) {
            u32 h = hist[bin];
            if (cum + h >= (u32)KSEL) break;
            cum += h;
        }
        if (bin < 0) bin = 0;
        sb_B1 = bin; sb_cntAbove = (int)cum;
    }
    __syncthreads();
    int B1 = sb_B1;
    int cntAbove = sb_cntAbove;

    // round 2: next 12 bits within bin B1
    for (int i = tid; i < 4096; i += 1024) hist[i] = 0;
    __syncthreads();
    for (int i = tid; i < m; i += 1024) {
        u32 k = fkey(g_cand_val[b][i]);
        if ((int)(k >> 20) == B1) atomicAdd(&hist[(k >> 8) & 0xFFF], 1u);
    }
    __syncthreads();
    if (tid == 0) {
        u32 cum = (u32)cntAbove; int bin = 4095;
        for (; bin >= 0; --bin) {
            u32 h = hist[bin];
            if (cum + h >= (u32)KSEL) break;
            cum += h;
        }
        if (bin < 0) bin = 0;
        sb_need2 = KSEL - (int)cum;
        sb_P = (((u32)B1) << 12) | (u32)bin;
    }
    __syncthreads();
    u32 P = sb_P;
    int need2 = sb_need2;

    // round 3: exact ranking of tie bucket (value desc, flat idx asc)
    for (int i = tid; i < m; i += 1024) {
        u32 k = fkey(g_cand_val[b][i]);
        if ((k >> 8) == P) {
            int p = atomicAdd(&s_tie_cnt, 1);
            if (p < 1024) { s_tie_key[p] = k; s_tie_idx[p] = g_cand_idx[b][i]; }
        }
    }
    __syncthreads();
    int ne = min(s_tie_cnt, 1024);
    for (int j = tid; j < ne; j += 1024) {
        u32 kj = s_tie_key[j]; int ij = s_tie_idx[j]; int r = 0;
        for (int i = 0; i < ne; i++) {
            u32 ki = s_tie_key[i];
            if (ki > kj || (ki == kj && s_tie_idx[i] < ij)) r++;
        }
        s_tie_sel[j] = (r < need2) ? 1 : 0;
    }
    __syncthreads();

    // emit exact top-K (unordered)
    for (int i = tid; i < m; i += 1024) {
        float v = g_cand_val[b][i];
        u32 k = fkey(v);
        if ((k >> 8) > P) {
            int p = atomicAdd(&s_out_cnt, 1);
            if (p < KSEL) { g_sel_val[b][p] = v; g_sel_idx[b][p] = g_cand_idx[b][i]; }
        }
    }
    __syncthreads();
    for (int j = tid; j < ne; j += 1024) {
        if (s_tie_sel[j]) {
            int p = atomicAdd(&s_out_cnt, 1);
            if (p < KSEL) { g_sel_val[b][p] = ikey(s_tie_key[j]); g_sel_idx[b][p] = s_tie_idx[j]; }
        }
    }
    __syncthreads();
    int cnt = min(s_out_cnt, KSEL);
    if (tid == 0) g_sel_cnt[b] = cnt;

    // bitonic sort descending by (value, then ascending flat idx) — matches top_k order
    for (int i = tid; i < SORTN; i += 1024) {
        if (i < cnt) {
            u32 k = fkey(g_sel_val[b][i]);
            u32 lo = 0xFFFFFFFFu - (u32)g_sel_idx[b][i];
            skey[i] = (((u64)k) << 32) | lo;
        } else {
            skey[i] = 0ull;
        }
    }
    __syncthreads();
    for (int k2 = 2; k2 <= SORTN; k2 <<= 1) {
        for (int j = k2 >> 1; j > 0; j >>= 1) {
            for (int i = tid; i < SORTN; i += 1024) {
                int ixj = i ^ j;
                if (ixj > i) {
                    bool descRegion = ((i & k2) == 0);
                    u64 a = skey[i], c = skey[ixj];
                    bool sw = descRegion ? (a < c) : (a > c);
                    if (sw) { skey[i] = c; skey[ixj] = a; }
                }
            }
            __syncthreads();
        }
    }
    for (int i = tid; i < cnt; i += 1024) {
        u64 s = skey[i];
        g_sel_val[b][i] = ikey((u32)(s >> 32));
        g_sel_idx[b][i] = (int)(0xFFFFFFFFu - (u32)s);
    }
}

// ---------------- kernel 5: decode boxes + sigmoid ----------------
__global__ void k_decode(const float* __restrict__ b0, const float* __restrict__ b1,
                         const float* __restrict__ b2, const float* __restrict__ b3,
                         const float* __restrict__ b4, const float* __restrict__ anchors) {
    int t = blockIdx.x * blockDim.x + threadIdx.x;
    if (t >= BATCH * NSLOT) return;
    int b = t / NSLOT;
    int k = t - b * NSLOT;
    int cnt = g_sel_cnt[b];
    if (k >= cnt) {
        g_nms_box[b][k] = make_float4(0.f, 0.f, 0.f, 0.f);
        g_nms_score[b][k] = -INFINITY;
        g_nms_cls[b][k] = 0;
        return;
    }
    float v = g_sel_val[b][k];
    int flat = g_sel_idx[b][k];
    int anchor = flat / NCLS;
    int cls = flat - anchor * NCLS;

    const float* bp; int hw, loc;
    if (anchor < 36864)      { bp = b0; hw = 4096; loc = anchor; }
    else if (anchor < 46080) { bp = b1; hw = 1024; loc = anchor - 36864; }
    else if (anchor < 48384) { bp = b2; hw = 256;  loc = anchor - 46080; }
    else if (anchor < 48960) { bp = b3; hw = 64;   loc = anchor - 48384; }
    else                     { bp = b4; hw = 16;   loc = anchor - 48960; }
    int a = loc % NANCH;
    int pix = loc / NANCH;

    const float* q = bp + ((long)b * 36 + a * 4) * hw + pix;
    float ty = __ldg(q);
    float tx = __ldg(q + hw);
    float th = __ldg(q + 2 * hw);
    float tw = __ldg(q + 3 * hw);

    float4 anc = __ldg((const float4*)(anchors + 4 * anchor)); // y1,x1,y2,x2
    float ya = (anc.x + anc.z) * 0.5f;
    float xa = (anc.y + anc.w) * 0.5f;
    float ha = anc.z - anc.x;
    float wa = anc.w - anc.y;
    float w = expf(tw) * wa;
    float h = expf(th) * ha;
    float yc = ty * ha + ya;
    float xc = tx * wa + xa;

    g_nms_box[b][k] = make_float4(xc - w * 0.5f, yc - h * 0.5f,
                                  xc + w * 0.5f, yc + h * 0.5f);
    g_nms_score[b][k] = __fdiv_rn(1.0f, 1.0f + expf(-v));
    g_nms_cls[b][k] = cls;
}

// ---------------- kernel 6: gaussian soft-NMS, 1 CTA per image ----------------
__global__ void __launch_bounds__(1024, 1) k_nms(float* __restrict__ out) {
    int b = blockIdx.x;
    int tid = threadIdx.x;
    float4 bx[5];
    float sc[5], ar[5];
    int cl[5];
    #pragma unroll
    for (int q = 0; q < 5; q++) {
        int s = q * 1024 + tid;
        bx[q] = g_nms_box[b][s];
        sc[q] = g_nms_score[b][s];
        cl[q] = g_nms_cls[b][s];
        ar[q] = (bx[q].z - bx[q].x) * (bx[q].w - bx[q].y);
    }
    __shared__ u64 s_warp[32];
    __shared__ u64 s_best;
    float* o = out + b * (NDET * 6);

    for (int it = 0; it < NDET; it++) {
        u64 best = 0;
        #pragma unroll
        for (int q = 0; q < 5; q++) {
            int s = q * 1024 + tid;
            u64 p = (((u64)fkey(sc[q])) << 32) | (u32)(NSLOT - 1 - s);
            if (p > best) best = p;
        }
        #pragma unroll
        for (int off = 16; off > 0; off >>= 1) {
            u64 oth = __shfl_xor_sync(0xFFFFFFFFu, best, off);
            if (oth > best) best = oth;
        }
        if ((tid & 31) == 0) s_warp[tid >> 5] = best;
        __syncthreads();
        if (tid < 32) {
            u64 v = s_warp[tid];
            #pragma unroll
            for (int off = 16; off > 0; off >>= 1) {
                u64 oth = __shfl_xor_sync(0xFFFFFFFFu, v, off);
                if (oth > v) v = oth;
            }
            if (tid == 0) s_best = v;
        }
        __syncthreads();
        u64 B = s_best;
        int si = NSLOT - 1 - (int)(B & 0xFFFFFFFFu);
        float ssel = ikey((u32)(B >> 32));
        float4 sb = g_nms_box[b][si];        // broadcast read
        float sar = (sb.z - sb.x) * (sb.w - sb.y);

        if ((si & 1023) == tid) {            // owner emits detection row
            int q = si >> 10;
            o[it * 6 + 0] = bx[q].x;
            o[it * 6 + 1] = bx[q].y;
            o[it * 6 + 2] = bx[q].z;
            o[it * 6 + 3] = bx[q].w;
            o[it * 6 + 4] = ssel;
            o[it * 6 + 5] = (float)cl[q];
        }
        // decay
        #pragma unroll
        for (int q = 0; q < 5; q++) {
            float x1 = fmaxf(sb.x, bx[q].x);
            float y1 = fmaxf(sb.y, bx[q].y);
            float x2 = fminf(sb.z, bx[q].z);
            float y2 = fminf(sb.w, bx[q].w);
            float iw = fmaxf(x2 - x1, 0.0f);
            float ih = fmaxf(y2 - y1, 0.0f);
            float inter = iw * ih;
            if (inter > 0.0f) {
                float iou = __fdiv_rn(inter, ((sar + ar[q]) - inter) + 1e-8f);
                float t2 = iou * iou;
                sc[q] *= expf(-(t2 + t2));   // exp(-(iou^2)/0.5), /0.5 is exact *2
            }
        }
        if ((si & 1023) == tid) sc[si >> 10] = -INFINITY;
    }
}

// ---------------- launch ----------------
extern "C" void kernel_launch(void* const* d_in, const int* in_sizes, int n_in,
                              void* d_out, int out_size) {
    const float *cls[5] = {0,0,0,0,0}, *box[5] = {0,0,0,0,0}, *anch = 0;
    for (int i = 0; i < n_in; i++) {
        const float* p = (const float*)d_in[i];
        switch (in_sizes[i]) {
            case 53084160: cls[0] = p; break;
            case 13271040: cls[1] = p; break;
            case 3317760:  cls[2] = p; break;
            case 829440:   cls[3] = p; break;
            case 207360:   cls[4] = p; break;
            case 2359296:  box[0] = p; break;
            case 589824:   box[1] = p; break;
            case 147456:   box[2] = p; break;
            case 36864:    box[3] = p; break;
            case 9216:     box[4] = p; break;
            case 196416:   anch   = p; break;
            default: break;
        }
    }
    static const int HWs[5] = {64, 32, 16, 8, 4};
    static const int AOFF[5] = {0, 36864, 46080, 48384, 48960};

    cudaFuncSetAttribute(k_select, cudaFuncAttributeMaxDynamicSharedMemorySize, 65536);

    k_zero<<<128, 256>>>();
    for (int l = 0; l < 5; l++) {
        int chw = 810 * HWs[l] * HWs[l];
        int ns = (chw + 255) / 256;
        int threads = BATCH * ns;
        k_sample<<<(threads + 255) / 256, 256>>>(cls[l], chw, ns);
    }
    k_thresh<<<1, 32>>>();
    for (int l = 0; l < 5; l++) {
        int W = HWs[l];
        int chw4 = 810 * W * W / 4;
        int gx = (chw4 + 2047) / 2048;
        dim3 g(gx, BATCH);
        int shW = (l == 0) ? 6 : (l == 1) ? 5 : (l == 2) ? 4 : (l == 3) ? 3 : 2;
        k_compact<<<g, 256>>>(cls[l], chw4, 2 * shW, AOFF[l]);
    }
    k_select<<<BATCH, 1024, 65536>>>();
    k_decode<<<(BATCH * NSLOT + 255) / 256, 256>>>(box[0], box[1], box[2], box[3], box[4], anch);
    k_nms<<<BATCH, 1024>>>((float*)d_out);
}

// round 4
// speedup vs baseline: 1.1848x; 1.1848x over previous
#include <cuda_runtime.h>
#include <math.h>

#define BATCH 16
#define NCLS 90
#define NANCH 9
#define KSEL 5000
#define NSLOT 5120
#define NDET 100
#define CAND_CAP 131072
#define STAGE_CAP 2048
#define S_TARGET 384
#define NS_TOTAL 17264

typedef unsigned long long u64;
typedef unsigned int u32;

// ---------------- device scratch (static, no runtime alloc) ----------------
__device__ u32   g_hist[BATCH][2048];
__device__ float g_thr[BATCH];
__device__ int   g_cand_cnt[BATCH];
__device__ float g_cand_val[BATCH][CAND_CAP];
__device__ int   g_cand_idx[BATCH][CAND_CAP];
__device__ float4 g_nms_box[BATCH][NSLOT];
__device__ float  g_nms_score[BATCH][NSLOT];
__device__ int    g_nms_cls[BATCH][NSLOT];
__device__ u32    g_nms_org[BATCH][NSLOT];
__device__ u32    g_nms_fidx[BATCH][NSLOT];

__device__ __forceinline__ u32 fkey(float f) {
    u32 u = __float_as_uint(f);
    return u ^ ((u32)((int)u >> 31) | 0x80000000u);   // monotonic: f1<f2 <=> key1<key2
}
__device__ __forceinline__ float ikey(u32 k) {
    u32 u = (k & 0x80000000u) ? (k ^ 0x80000000u) : ~k;
    return __uint_as_float(u);
}

// ---------------- kernel 0: zero counters/hist ----------------
__global__ void k_zero() {
    int t = blockIdx.x * blockDim.x + threadIdx.x;
    if (t < BATCH * 2048) ((u32*)g_hist)[t] = 0;
    if (t < BATCH) g_cand_cnt[t] = 0;
}

// ---------------- kernel 1: sampled histogram (1/64), all levels, one launch ----------------
__global__ void k_sample(const float* __restrict__ c0, const float* __restrict__ c1,
                         const float* __restrict__ c2, const float* __restrict__ c3,
                         const float* __restrict__ c4) {
    int t = blockIdx.x * blockDim.x + threadIdx.x;
    if (t >= BATCH * NS_TOTAL) return;
    int b = t / NS_TOTAL;
    int r = t - b * NS_TOTAL;
    const float* cls; int chw, i;
    if (r < 12960)      { cls = c0; chw = 3317760; i = r; }
    else if (r < 16200) { cls = c1; chw = 829440;  i = r - 12960; }
    else if (r < 17010) { cls = c2; chw = 207360;  i = r - 16200; }
    else if (r < 17213) { cls = c3; chw = 51840;   i = r - 17010; }
    else                { cls = c4; chw = 12960;   i = r - 17213; }
    int off = i * 256;
    if (off + 4 > chw) return;
    float4 v = __ldg((const float4*)(cls + (long)b * chw + off));
    atomicAdd(&g_hist[b][fkey(v.x) >> 21], 1u);
    atomicAdd(&g_hist[b][fkey(v.y) >> 21], 1u);
    atomicAdd(&g_hist[b][fkey(v.z) >> 21], 1u);
    atomicAdd(&g_hist[b][fkey(v.w) >> 21], 1u);
}

// ---------------- kernel 2: per-image threshold from sample hist ----------------
__global__ void k_thresh() {
    int b = threadIdx.x;
    if (b >= BATCH) return;
    u32 cum = 0;
    int bin = 2047;
    for (; bin >= 0; --bin) {
        cum += g_hist[b][bin];
        if (cum >= S_TARGET) break;
    }
    if (bin < 0) bin = 0;
    u32 kthr = ((u32)bin) << 21;
    u32 u = (kthr & 0x80000000u) ? (kthr ^ 0x80000000u) : ~kthr;
    g_thr[b] = __uint_as_float(u);
}

// ---------------- kernel 3: full scan + compaction, all levels, one launch ----------------
__global__ void k_compact(const float* __restrict__ c0, const float* __restrict__ c1,
                          const float* __restrict__ c2, const float* __restrict__ c3,
                          const float* __restrict__ c4) {
    __shared__ float s_val[STAGE_CAP];
    __shared__ int   s_idx[STAGE_CAP];
    __shared__ int   s_cnt, s_base;
    int b = blockIdx.y;
    int tid = threadIdx.x;
    int blk = blockIdx.x;
    const float* cls; int chw4, shHW, aoff, lb;
    if (blk < 405)      { cls = c0; chw4 = 829440; shHW = 12; aoff = 0;     lb = blk; }
    else if (blk < 507) { cls = c1; chw4 = 207360; shHW = 10; aoff = 36864; lb = blk - 405; }
    else if (blk < 533) { cls = c2; chw4 = 51840;  shHW = 8;  aoff = 46080; lb = blk - 507; }
    else if (blk < 540) { cls = c3; chw4 = 12960;  shHW = 6;  aoff = 48384; lb = blk - 533; }
    else                { cls = c4; chw4 = 3240;   shHW = 4;  aoff = 48960; lb = blk - 540; }

    if (tid == 0) s_cnt = 0;
    __syncthreads();
    float thr = g_thr[b];
    const float4* base = (const float4*)cls + (long)b * chw4;
    int i0 = lb * 2048 + tid;

    float4 v[8];
    #pragma unroll
    for (int g = 0; g < 8; g++) {
        int i4 = i0 + g * 256;
        v[g] = (i4 < chw4) ? __ldg(base + i4)
                           : make_float4(-INFINITY, -INFINITY, -INFINITY, -INFINITY);
    }
    #pragma unroll
    for (int g = 0; g < 8; g++) {
        int i4 = i0 + g * 256;
        #pragma unroll
        for (int j = 0; j < 4; j++) {
            float f = (j == 0) ? v[g].x : (j == 1) ? v[g].y : (j == 2) ? v[g].z : v[g].w;
            if (f >= thr) {
                int lin = i4 * 4 + j;
                int ch = lin >> shHW;                 // 0..809 (= a*90 + c)
                int pix = lin & ((1 << shHW) - 1);    // h*W + w
                int a = ch / NCLS;
                int c = ch - a * NCLS;
                int flat = (aoff + pix * NANCH + a) * NCLS + c;
                int p = atomicAdd(&s_cnt, 1);
                if (p < STAGE_CAP) { s_val[p] = f; s_idx[p] = flat; }
            }
        }
    }
    __syncthreads();
    if (tid == 0) {
        int n = min(s_cnt, STAGE_CAP);
        s_base = atomicAdd(&g_cand_cnt[b], n);
        s_cnt = n;
    }
    __syncthreads();
    for (int i = tid; i < s_cnt; i += 256) {
        int gi = s_base + i;
        if (gi < CAND_CAP) {
            g_cand_val[b][gi] = s_val[i];
            g_cand_idx[b][gi] = s_idx[i];
        }
    }
}

// ---------------- decode helper (fused into select) ----------------
__device__ __forceinline__ void decode_store(
    int b, int slot, float v, int flat,
    const float* __restrict__ b0, const float* __restrict__ b1,
    const float* __restrict__ b2, const float* __restrict__ b3,
    const float* __restrict__ b4, const float* __restrict__ anchors)
{
    int anchor = flat / NCLS;
    int cls = flat - anchor * NCLS;

    const float* bp; int hw, loc;
    if (anchor < 36864)      { bp = b0; hw = 4096; loc = anchor; }
    else if (anchor < 46080) { bp = b1; hw = 1024; loc = anchor - 36864; }
    else if (anchor < 48384) { bp = b2; hw = 256;  loc = anchor - 46080; }
    else if (anchor < 48960) { bp = b3; hw = 64;   loc = anchor - 48384; }
    else                     { bp = b4; hw = 16;   loc = anchor - 48960; }
    int a = loc % NANCH;
    int pix = loc / NANCH;

    const float* q = bp + ((long)b * 36 + a * 4) * hw + pix;
    float ty = __ldg(q);
    float tx = __ldg(q + hw);
    float th = __ldg(q + 2 * hw);
    float tw = __ldg(q + 3 * hw);

    float4 anc = __ldg((const float4*)(anchors + 4 * anchor)); // y1,x1,y2,x2
    float ya = (anc.x + anc.z) * 0.5f;
    float xa = (anc.y + anc.w) * 0.5f;
    float ha = anc.z - anc.x;
    float wa = anc.w - anc.y;
    float w = expf(tw) * wa;
    float h = expf(th) * ha;
    float yc = ty * ha + ya;
    float xc = tx * wa + xa;

    g_nms_box[b][slot] = make_float4(xc - w * 0.5f, yc - h * 0.5f,
                                     xc + w * 0.5f, yc + h * 0.5f);
    g_nms_score[b][slot] = __fdiv_rn(1.0f, 1.0f + expf(-v));
    g_nms_cls[b][slot] = cls;
    g_nms_org[b][slot] = fkey(v);
    g_nms_fidx[b][slot] = (u32)flat;
}

// ---------------- kernel 4: exact top-K select (unordered) + fused decode ----------------
__global__ void __launch_bounds__(1024, 1) k_select(
    const float* __restrict__ b0, const float* __restrict__ b1,
    const float* __restrict__ b2, const float* __restrict__ b3,
    const float* __restrict__ b4, const float* __restrict__ anchors)
{
    __shared__ u32 hist[4096];
    __shared__ int sb_B1, sb_cntAbove, sb_need2;
    __shared__ u32 sb_P;
    __shared__ int s_tie_cnt, s_out_cnt;
    __shared__ u32 s_tie_key[1024];
    __shared__ int s_tie_idx[1024];
    __shared__ unsigned char s_tie_sel[1024];

    int b = blockIdx.x;
    int tid = threadIdx.x;
    int m = min(g_cand_cnt[b], CAND_CAP);

    // round 1: histogram of top 12 key bits
    for (int i = tid; i < 4096; i += 1024) hist[i] = 0;
    if (tid == 0) { s_tie_cnt = 0; s_out_cnt = 0; }
    __syncthreads();
    for (int i = tid; i < m; i += 1024)
        atomicAdd(&hist[fkey(g_cand_val[b][i]) >> 20], 1u);
    __syncthreads();
    if (tid == 0) {
        u32 cum = 0; int bin = 4095;
        for (; bin >= 0; --bin) {
            u32 h = hist[bin];
            if (cum + h >= (u32)KSEL) break;
            cum += h;
        }
        if (bin < 0) bin = 0;
        sb_B1 = bin; sb_cntAbove = (int)cum;
    }
    __syncthreads();
    int B1 = sb_B1;
    int cntAbove = sb_cntAbove;

    // round 2: next 12 bits within bin B1
    for (int i = tid; i < 4096; i += 1024) hist[i] = 0;
    __syncthreads();
    for (int i = tid; i < m; i += 1024) {
        u32 k = fkey(g_cand_val[b][i]);
        if ((int)(k >> 20) == B1) atomicAdd(&hist[(k >> 8) & 0xFFF], 1u);
    }
    __syncthreads();
    if (tid == 0) {
        u32 cum = (u32)cntAbove; int bin = 4095;
        for (; bin >= 0; --bin) {
            u32 h = hist[bin];
            if (cum + h >= (u32)KSEL) break;
            cum += h;
        }
        if (bin < 0) bin = 0;
        sb_need2 = KSEL - (int)cum;
        sb_P = (((u32)B1) << 12) | (u32)bin;
    }
    __syncthreads();
    u32 P = sb_P;
    int need2 = sb_need2;

    // round 3: exact ranking of tie bucket (value desc, flat idx asc)
    for (int i = tid; i < m; i += 1024) {
        u32 k = fkey(g_cand_val[b][i]);
        if ((k >> 8) == P) {
            int p = atomicAdd(&s_tie_cnt, 1);
            if (p < 1024) { s_tie_key[p] = k; s_tie_idx[p] = g_cand_idx[b][i]; }
        }
    }
    __syncthreads();
    int ne = min(s_tie_cnt, 1024);
    for (int j = tid; j < ne; j += 1024) {
        u32 kj = s_tie_key[j]; int ij = s_tie_idx[j]; int r = 0;
        for (int i = 0; i < ne; i++) {
            u32 ki = s_tie_key[i];
            if (ki > kj || (ki == kj && s_tie_idx[i] < ij)) r++;
        }
        s_tie_sel[j] = (r < need2) ? 1 : 0;
    }
    __syncthreads();

    // emit exact top-K (unordered) with fused decode
    for (int i = tid; i < m; i += 1024) {
        float v = g_cand_val[b][i];
        u32 k = fkey(v);
        if ((k >> 8) > P) {
            int p = atomicAdd(&s_out_cnt, 1);
            if (p < KSEL) decode_store(b, p, v, g_cand_idx[b][i], b0, b1, b2, b3, b4, anchors);
        }
    }
    __syncthreads();
    for (int j = tid; j < ne; j += 1024) {
        if (s_tie_sel[j]) {
            int p = atomicAdd(&s_out_cnt, 1);
            if (p < KSEL) decode_store(b, p, ikey(s_tie_key[j]), s_tie_idx[j], b0, b1, b2, b3, b4, anchors);
        }
    }
    __syncthreads();
    int cnt = min(s_out_cnt, KSEL);
    // padding slots
    for (int k = cnt + tid; k < NSLOT; k += 1024) {
        g_nms_box[b][k] = make_float4(0.f, 0.f, 0.f, 0.f);
        g_nms_score[b][k] = -INFINITY;
        g_nms_cls[b][k] = 0;
        g_nms_org[b][k] = 0u;
        g_nms_fidx[b][k] = 0xFFFFFFFFu;
    }
}

// ---------------- kernel 5: gaussian soft-NMS, 1 CTA per image ----------------
extern __shared__ float4 nms_sbox[];
__global__ void __launch_bounds__(1024, 1) k_nms(float* __restrict__ out) {
    int b = blockIdx.x;
    int tid = threadIdx.x;
    float sc[5], ar[5];
    u32 org[5];
    u64 lo[5];
    #pragma unroll
    for (int q = 0; q < 5; q++) {
        int s = q * 1024 + tid;
        float4 v = g_nms_box[b][s];
        nms_sbox[s] = v;
        sc[q] = g_nms_score[b][s];
        org[q] = g_nms_org[b][s];
        u32 fidx = g_nms_fidx[b][s];
        lo[q] = (((u64)(~fidx)) << 32) | (u32)s;
        ar[q] = (v.z - v.x) * (v.w - v.y);
    }
    __shared__ u64 s_whi[32], s_wlo[32];
    __shared__ u64 s_bhi, s_blo;
    float* o = out + b * (NDET * 6);
    __syncthreads();

    for (int it = 0; it < NDET; it++) {
        // argmax with 128-bit comparator: (curr score desc, orig logit desc, flat idx asc)
        u64 bhi = 0ull, blo = 0ull;
        #pragma unroll
        for (int q = 0; q < 5; q++) {
            u64 hi = (((u64)fkey(sc[q])) << 32) | org[q];
            if (hi > bhi || (hi == bhi && lo[q] > blo)) { bhi = hi; blo = lo[q]; }
        }
        #pragma unroll
        for (int off = 16; off > 0; off >>= 1) {
            u64 ohi = __shfl_xor_sync(0xFFFFFFFFu, bhi, off);
            u64 olo = __shfl_xor_sync(0xFFFFFFFFu, blo, off);
            if (ohi > bhi || (ohi == bhi && olo > blo)) { bhi = ohi; blo = olo; }
        }
        if ((tid & 31) == 0) { s_whi[tid >> 5] = bhi; s_wlo[tid >> 5] = blo; }
        __syncthreads();
        if (tid < 32) {
            bhi = s_whi[tid]; blo = s_wlo[tid];
            #pragma unroll
            for (int off = 16; off > 0; off >>= 1) {
                u64 ohi = __shfl_xor_sync(0xFFFFFFFFu, bhi, off);
                u64 olo = __shfl_xor_sync(0xFFFFFFFFu, blo, off);
                if (ohi > bhi || (ohi == bhi && olo > blo)) { bhi = ohi; blo = olo; }
            }
            if (tid == 0) { s_bhi = bhi; s_blo = blo; }
        }
        __syncthreads();
        u64 BH = s_bhi, BL = s_blo;
        int si = (int)(BL & 0xFFFFFFFFull);
        float ssel = ikey((u32)(BH >> 32));
        float4 sb = nms_sbox[si];
        float sar = (sb.z - sb.x) * (sb.w - sb.y);

        if ((si & 1023) == tid) {            // owner emits detection row + kills slot
            o[it * 6 + 0] = sb.x;
            o[it * 6 + 1] = sb.y;
            o[it * 6 + 2] = sb.z;
            o[it * 6 + 3] = sb.w;
            o[it * 6 + 4] = ssel;
            o[it * 6 + 5] = (float)g_nms_cls[b][si];
            sc[si >> 10] = -INFINITY;
        }
        // decay
        #pragma unroll
        for (int q = 0; q < 5; q++) {
            float4 bq = nms_sbox[q * 1024 + tid];
            float x1 = fmaxf(sb.x, bq.x);
            float y1 = fmaxf(sb.y, bq.y);
            float x2 = fminf(sb.z, bq.z);
            float y2 = fminf(sb.w, bq.w);
            float iw = fmaxf(x2 - x1, 0.0f);
            float ih = fmaxf(y2 - y1, 0.0f);
            float inter = iw * ih;
            if (inter > 0.0f) {
                float iou = __fdiv_rn(inter, ((sar + ar[q]) - inter) + 1e-8f);
                float t2 = iou * iou;
                sc[q] *= expf(-(t2 + t2));   // exp(-(iou^2)/0.5), /0.5 is exact *2
            }
        }
    }
}

// ---------------- launch ----------------
extern "C" void kernel_launch(void* const* d_in, const int* in_sizes, int n_in,
                              void* d_out, int out_size) {
    const float *cls[5] = {0,0,0,0,0}, *box[5] = {0,0,0,0,0}, *anch = 0;
    for (int i = 0; i < n_in; i++) {
        const float* p = (const float*)d_in[i];
        switch (in_sizes[i]) {
            case 53084160: cls[0] = p; break;
            case 13271040: cls[1] = p; break;
            case 3317760:  cls[2] = p; break;
            case 829440:   cls[3] = p; break;
            case 207360:   cls[4] = p; break;
            case 2359296:  box[0] = p; break;
            case 589824:   box[1] = p; break;
            case 147456:   box[2] = p; break;
            case 36864:    box[3] = p; break;
            case 9216:     box[4] = p; break;
            case 196416:   anch   = p; break;
            default: break;
        }
    }
    cudaFuncSetAttribute(k_nms, cudaFuncAttributeMaxDynamicSharedMemorySize, NSLOT * 16);

    k_zero<<<64, 512>>>();
    k_sample<<<(BATCH * NS_TOTAL + 255) / 256, 256>>>(cls[0], cls[1], cls[2], cls[3], cls[4]);
    k_thresh<<<1, 32>>>();
    {
        dim3 g(542, BATCH);
        k_compact<<<g, 256>>>(cls[0], cls[1], cls[2], cls[3], cls[4]);
    }
    k_select<<<BATCH, 1024>>>(box[0], box[1], box[2], box[3], box[4], anch);
    k_nms<<<BATCH, 1024, NSLOT * 16>>>((float*)d_out);
}